// round 2
// baseline (speedup 1.0000x reference)
#include <cuda_runtime.h>
#include <math.h>

// ---------------------------------------------------------------------------
// Problem constants
// ---------------------------------------------------------------------------
static constexpr int N_ = 10000;
static constexpr int E_ = 320000;

// Output layout (element offsets into d_out, float32), tuple order:
//   node_emb   [N,8]    @ 0
//   edge_emb   [E,8]    @ 80000
//   recon_node [N,64]   @ 2640000
//   recon_edge [E,32]   @ 3280000
//   adj        [N,N]    @ 13520000
//   coord_out  [N,3]    @ 113520000      (total 113550000)
static constexpr size_t OFF_NODE_EMB   = 0;
static constexpr size_t OFF_EDGE_EMB   = 80000;
static constexpr size_t OFF_RECON_NODE = 2640000;
static constexpr size_t OFF_RECON_EDGE = 3280000;
static constexpr size_t OFF_ADJ        = 13520000;
static constexpr size_t OFF_COORD      = 113520000;

// ---------------------------------------------------------------------------
// Scratch (__device__ globals; no allocation allowed)
// ---------------------------------------------------------------------------
__device__ __align__(16) float g_P[N_ * 256];   // [0:128)=b1 + nf@W1[0:64], [128:256)=nf@W1[64:128]
__device__ float g_agg[N_ * 32];                // scatter-add of edge_out by row

// ---------------------------------------------------------------------------
// init: zero agg, seed coord_out with coords
// ---------------------------------------------------------------------------
__global__ void init_kernel(const float* __restrict__ coords,
                            float* __restrict__ out_coord)
{
    int i = blockIdx.x * blockDim.x + threadIdx.x;
    int stride = gridDim.x * blockDim.x;
    for (int k = i; k < N_ * 32; k += stride) g_agg[k] = 0.f;
    for (int k = i; k < N_ * 3;  k += stride) out_coord[k] = coords[k];
}

// ---------------------------------------------------------------------------
// Node projections: g_P[n] = [ b1 + nf[n] @ W1[0:64] , nf[n] @ W1[64:128] ]
// 16 nodes per block, thread j owns hidden column j.
// ---------------------------------------------------------------------------
__global__ __launch_bounds__(128) void proj_kernel(
    const float* __restrict__ nf, const float* __restrict__ w1,
    const float* __restrict__ b1)
{
    __shared__ float sIn[16][65];
    int tid = threadIdx.x;
    int n0 = blockIdx.x * 16;
    if (n0 >= N_) return;

    for (int t = tid; t < 16 * 64; t += 128) {
        int g = t >> 6, i = t & 63;
        sIn[g][i] = nf[(n0 + g) * 64 + i];
    }
    __syncthreads();

    float pa[16], pb[16];
    float bb = b1[tid];
#pragma unroll
    for (int g = 0; g < 16; g++) { pa[g] = bb; pb[g] = 0.f; }

    for (int i = 0; i < 64; i++) {
        float wa = w1[i * 128 + tid];
        float wb = w1[(64 + i) * 128 + tid];
#pragma unroll
        for (int g = 0; g < 16; g++) {
            float v = sIn[g][i];
            pa[g] += v * wa;
            pb[g] += v * wb;
        }
    }
#pragma unroll
    for (int g = 0; g < 16; g++) {
        g_P[(size_t)(n0 + g) * 256 + tid]       = pa[g];
        g_P[(size_t)(n0 + g) * 256 + 128 + tid] = pb[g];
    }
}

// ---------------------------------------------------------------------------
// Edge kernel: per warp, 4 edges at a time.
//   h = relu(P_a[row] + P_b[col] + attr @ W1c + radial*w1d)   (128)
//   edge_out = h @ W2 + b2                                     (32)
//   coord weight MLP -> atomic scatter into coord_out
//   atomic scatter edge_out into g_agg
//   edge_emb = edge_out @ fcW + fcb  -> d_out
//   recon_edge = edge_emb @ decW + decb -> d_out
// ---------------------------------------------------------------------------
__global__ __launch_bounds__(128) void edge_kernel(
    const int*   __restrict__ ei,
    const float* __restrict__ edge_attr,
    const float* __restrict__ coords,
    const float* __restrict__ ew1,
    const float* __restrict__ ew2,  const float* __restrict__ eb2,
    const float* __restrict__ cw1,  const float* __restrict__ cb1,
    const float* __restrict__ cw2,
    const float* __restrict__ fcw,  const float* __restrict__ fcb,
    const float* __restrict__ decw, const float* __restrict__ decb,
    float* __restrict__ out_edge_emb,
    float* __restrict__ out_recon_edge,
    float* __restrict__ out_coord)
{
    __shared__ __align__(16) float sW1c[32 * 128];   // W1 rows 128..159 (attr part)
    __shared__ __align__(16) float sW1d[128];        // W1 row 160 (radial)
    __shared__ __align__(16) float sW2t[32 * 132];   // W2 transposed, padded stride
    __shared__ float sB2[32];
    __shared__ float sCw1[64];
    __shared__ float sCmisc[4];                      // cb1[0],cb1[1],cw2[0],cw2[1]
    __shared__ float sFcW[256], sFcB[8];
    __shared__ float sDecW[256], sDecB[32];
    __shared__ __align__(16) float sH[4][4][128];
    __shared__ float sO[4][4][33];
    __shared__ float sEmb[4][4][8];

    int tid = threadIdx.x;
    for (int t = tid; t < 32 * 128; t += 128) sW1c[t] = ew1[128 * 128 + t];
    if (tid < 128) sW1d[tid] = ew1[160 * 128 + tid];
    for (int t = tid; t < 32 * 128; t += 128) {
        int k = t >> 7, j = t & 127;
        sW2t[k * 132 + j] = ew2[j * 32 + k];
    }
    if (tid < 32) sB2[tid] = eb2[tid];
    if (tid < 64) sCw1[tid] = cw1[tid];
    if (tid < 2)  { sCmisc[tid] = cb1[tid]; sCmisc[2 + tid] = cw2[tid]; }
    for (int t = tid; t < 256; t += 128) { sFcW[t] = fcw[t]; sDecW[t] = decw[t]; }
    if (tid < 8)  sFcB[tid] = fcb[tid];
    if (tid < 32) sDecB[tid] = decb[tid];
    __syncthreads();

    const int warp = tid >> 5, lane = tid & 31;
    const int ngroups = E_ / 4;

    for (int grp = blockIdx.x * 4 + warp; grp < ngroups; grp += gridDim.x * 4) {
        const int e0 = grp * 4;
        int row[4];
        float attr[4], nx[4], ny[4], nz[4];
        float4 h[4];

#pragma unroll
        for (int g = 0; g < 4; g++) {
            int e = e0 + g;
            row[g] = ei[e];
            int colg = ei[E_ + e];
            float cx = coords[row[g] * 3 + 0] - coords[colg * 3 + 0];
            float cy = coords[row[g] * 3 + 1] - coords[colg * 3 + 1];
            float cz = coords[row[g] * 3 + 2] - coords[colg * 3 + 2];
            float radial = cx * cx + cy * cy + cz * cz;
            float inv = 1.f / (sqrtf(radial) + 1.f);
            nx[g] = cx * inv; ny[g] = cy * inv; nz[g] = cz * inv;
            attr[g] = edge_attr[(size_t)e * 32 + lane];

            float4 pa = *(const float4*)(g_P + (size_t)row[g] * 256 + 4 * lane);
            float4 pb = *(const float4*)(g_P + (size_t)colg * 256 + 128 + 4 * lane);
            float4 wd = *(const float4*)(sW1d + 4 * lane);
            h[g].x = pa.x + pb.x + radial * wd.x;
            h[g].y = pa.y + pb.y + radial * wd.y;
            h[g].z = pa.z + pb.z + radial * wd.z;
            h[g].w = pa.w + pb.w + radial * wd.w;
        }

        // layer 1: attr part (K=32), attr broadcast via shfl
#pragma unroll 4
        for (int i = 0; i < 32; i++) {
            float4 w = *(const float4*)(sW1c + i * 128 + 4 * lane);
#pragma unroll
            for (int g = 0; g < 4; g++) {
                float a = __shfl_sync(0xffffffffu, attr[g], i);
                h[g].x += a * w.x;
                h[g].y += a * w.y;
                h[g].z += a * w.z;
                h[g].w += a * w.w;
            }
        }

        // relu, stage h
#pragma unroll
        for (int g = 0; g < 4; g++) {
            float4 v;
            v.x = fmaxf(h[g].x, 0.f);
            v.y = fmaxf(h[g].y, 0.f);
            v.z = fmaxf(h[g].z, 0.f);
            v.w = fmaxf(h[g].w, 0.f);
            *(float4*)(&sH[warp][g][4 * lane]) = v;
        }
        __syncwarp();

        // layer 2: lane owns output channel k = lane
        float out[4];
#pragma unroll
        for (int g = 0; g < 4; g++) out[g] = sB2[lane];
#pragma unroll 4
        for (int j4 = 0; j4 < 32; j4++) {
            float4 w = *(const float4*)(sW2t + lane * 132 + 4 * j4);
#pragma unroll
            for (int g = 0; g < 4; g++) {
                float4 hv = *(const float4*)(&sH[warp][g][4 * j4]);
                out[g] += w.x * hv.x + w.y * hv.y + w.z * hv.z + w.w * hv.w;
            }
        }

        // scatter edge_out into agg
#pragma unroll
        for (int g = 0; g < 4; g++)
            atomicAdd(&g_agg[(size_t)row[g] * 32 + lane], out[g]);

        // coord MLP + coord scatter
        float c0 = sCmisc[0], c1 = sCmisc[1], d0 = sCmisc[2], d1 = sCmisc[3];
#pragma unroll
        for (int g = 0; g < 4; g++) {
            float p0 = out[g] * sCw1[lane * 2 + 0];
            float p1 = out[g] * sCw1[lane * 2 + 1];
#pragma unroll
            for (int off = 16; off > 0; off >>= 1) {
                p0 += __shfl_xor_sync(0xffffffffu, p0, off);
                p1 += __shfl_xor_sync(0xffffffffu, p1, off);
            }
            float t0 = fmaxf(p0 + c0, 0.f);
            float t1 = fmaxf(p1 + c1, 0.f);
            float wc = t0 * d0 + t1 * d1;
            if (lane < 3) {
                float nv = (lane == 0) ? nx[g] : ((lane == 1) ? ny[g] : nz[g]);
                atomicAdd(&out_coord[(size_t)row[g] * 3 + lane], nv * wc);
            }
        }

        // stage edge_out for cross-lane matvecs
#pragma unroll
        for (int g = 0; g < 4; g++) sO[warp][g][lane] = out[g];
        __syncwarp();

        // edge embedding: lane -> (g = lane>>3, m = lane&7)
        {
            int g = lane >> 3, m = lane & 7;
            float acc = sFcB[m];
#pragma unroll
            for (int k = 0; k < 32; k++) acc += sO[warp][g][k] * sFcW[k * 8 + m];
            out_edge_emb[(size_t)(e0 + g) * 8 + m] = acc;
            sEmb[warp][g][m] = acc;
        }
        __syncwarp();

        // recon edge: lane owns output channel k = lane
#pragma unroll
        for (int g = 0; g < 4; g++) {
            float acc = sDecB[lane];
#pragma unroll
            for (int m = 0; m < 8; m++)
                acc += sEmb[warp][g][m] * sDecW[m * 32 + lane];
            out_recon_edge[(size_t)(e0 + g) * 32 + lane] = acc;
        }
        __syncwarp();
    }
}

// ---------------------------------------------------------------------------
// Node kernel: 16 nodes per block.
//   node_in = [nf(64), agg(32), coord_out(3)] -> h(128) -> out(64)
//   -> node_emb(8) -> recon_node(64)
// ---------------------------------------------------------------------------
__global__ __launch_bounds__(128) void node_kernel(
    const float* __restrict__ nf,
    const float* __restrict__ coord_out,
    const float* __restrict__ w1, const float* __restrict__ b1,
    const float* __restrict__ w2, const float* __restrict__ b2,
    const float* __restrict__ fcw, const float* __restrict__ fcb,
    const float* __restrict__ decw, const float* __restrict__ decb,
    float* __restrict__ out_node_emb,
    float* __restrict__ out_recon_node)
{
    __shared__ float sIn[16][100];
    __shared__ float sH[16][128];
    __shared__ float sOut[16][65];
    __shared__ float sEmb[16][9];

    int tid = threadIdx.x;
    int n0 = blockIdx.x * 16;
    if (n0 >= N_) return;

    for (int t = tid; t < 16 * 99; t += 128) {
        int g = t / 99, i = t % 99;
        int n = n0 + g;
        float v;
        if (i < 64)      v = nf[(size_t)n * 64 + i];
        else if (i < 96) v = g_agg[(size_t)n * 32 + (i - 64)];
        else             v = coord_out[(size_t)n * 3 + (i - 96)];
        sIn[g][i] = v;
    }
    __syncthreads();

    // layer 1: thread tid owns hidden column
    {
        float h[16];
        float bb = b1[tid];
#pragma unroll
        for (int g = 0; g < 16; g++) h[g] = bb;
        for (int i = 0; i < 99; i++) {
            float w = w1[i * 128 + tid];
#pragma unroll
            for (int g = 0; g < 16; g++) h[g] += sIn[g][i] * w;
        }
#pragma unroll
        for (int g = 0; g < 16; g++) sH[g][tid] = fmaxf(h[g], 0.f);
    }
    __syncthreads();

    // layer 2: thread -> (k = tid&63, nodes gbase..gbase+7)
    {
        int k = tid & 63;
        int gbase = (tid >> 6) * 8;
        float o[8];
        float bb = b2[k];
#pragma unroll
        for (int q = 0; q < 8; q++) o[q] = bb;
        for (int j = 0; j < 128; j++) {
            float w = w2[j * 64 + k];
#pragma unroll
            for (int q = 0; q < 8; q++) o[q] += sH[gbase + q][j] * w;
        }
#pragma unroll
        for (int q = 0; q < 8; q++) sOut[gbase + q][k] = o[q];
    }
    __syncthreads();

    // embedding: thread -> (g = tid>>3, m = tid&7)
    {
        int g = tid >> 3, m = tid & 7;
        float acc = fcb[m];
#pragma unroll
        for (int k = 0; k < 64; k++) acc += sOut[g][k] * fcw[k * 8 + m];
        out_node_emb[(size_t)(n0 + g) * 8 + m] = acc;
        sEmb[g][m] = acc;
    }
    __syncthreads();

    // recon node
    {
        int k = tid & 63;
        int gbase = (tid >> 6) * 8;
#pragma unroll
        for (int q = 0; q < 8; q++) {
            int g = gbase + q;
            float acc = decb[k];
#pragma unroll
            for (int m = 0; m < 8; m++) acc += sEmb[g][m] * decw[m * 64 + k];
            out_recon_node[(size_t)(n0 + g) * 64 + k] = acc;
        }
    }
}

// ---------------------------------------------------------------------------
// adj kernel: 64x64 tile per block, 4x4 micro-tile per thread.
//   adj[i][j] = sigmoid(3*||ei-ej||^2 - 1) = sigmoid(qi + qj - 6*(ei.ej))
//   with q = 3*r - 0.5; diag forced to 0.
// ---------------------------------------------------------------------------
__global__ __launch_bounds__(256) void adj_kernel(
    const float* __restrict__ emb, float* __restrict__ adj)
{
    __shared__ float sA[64][8];
    __shared__ float sB[64][9];
    __shared__ float sQA[64], sQB[64];

    int tx = threadIdx.x, ty = threadIdx.y;
    int tid = ty * 16 + tx;
    int bi = blockIdx.y * 64, bj = blockIdx.x * 64;

    for (int t = tid; t < 512; t += 256) {
        int r = t >> 3, d = t & 7;
        int gi = bi + r, gj = bj + r;
        sA[r][d] = (gi < N_) ? emb[(size_t)gi * 8 + d] : 0.f;
        sB[r][d] = (gj < N_) ? emb[(size_t)gj * 8 + d] : 0.f;
    }
    __syncthreads();

    if (tid < 64) {
        float s = 0.f;
#pragma unroll
        for (int d = 0; d < 8; d++) s += sA[tid][d] * sA[tid][d];
        sQA[tid] = 3.f * s - 0.5f;
    } else if (tid < 128) {
        int r = tid - 64;
        float s = 0.f;
#pragma unroll
        for (int d = 0; d < 8; d++) s += sB[r][d] * sB[r][d];
        sQB[r] = 3.f * s - 0.5f;
    }
    __syncthreads();

    float a[4][8], b[4][8], qa[4], qb[4];
#pragma unroll
    for (int ii = 0; ii < 4; ii++) {
        qa[ii] = sQA[ty * 4 + ii];
#pragma unroll
        for (int d = 0; d < 8; d++) a[ii][d] = sA[ty * 4 + ii][d];
    }
#pragma unroll
    for (int jj = 0; jj < 4; jj++) {
        qb[jj] = sQB[tx * 4 + jj];
#pragma unroll
        for (int d = 0; d < 8; d++) b[jj][d] = sB[tx * 4 + jj][d];
    }

#pragma unroll
    for (int ii = 0; ii < 4; ii++) {
        int gi = bi + ty * 4 + ii;
        float r4[4];
#pragma unroll
        for (int jj = 0; jj < 4; jj++) {
            float dot = 0.f;
#pragma unroll
            for (int d = 0; d < 8; d++) dot += a[ii][d] * b[jj][d];
            float y = qa[ii] + qb[jj] - 6.f * dot;
            // sigmoid via exp2 (MUFU.EX2), explicit fast path
            float s = 1.f / (1.f + exp2f(-1.4426950408889634f * y));
            int gj = bj + tx * 4 + jj;
            if (gi == gj) s = 0.f;
            r4[jj] = s;
        }
        if (gi < N_) {
            int gj0 = bj + tx * 4;
            if (gj0 + 3 < N_) {
                *(float4*)(adj + (size_t)gi * N_ + gj0) =
                    make_float4(r4[0], r4[1], r4[2], r4[3]);
            } else {
                for (int jj = 0; jj < 4; jj++)
                    if (gj0 + jj < N_) adj[(size_t)gi * N_ + gj0 + jj] = r4[jj];
            }
        }
    }
}

// ---------------------------------------------------------------------------
// launch
// ---------------------------------------------------------------------------
extern "C" void kernel_launch(void* const* d_in, const int* in_sizes, int n_in,
                              void* d_out, int out_size)
{
    const float* node_feats = (const float*)d_in[0];
    const int*   edge_index = (const int*)  d_in[1];
    const float* edge_attr  = (const float*)d_in[2];
    const float* coords     = (const float*)d_in[3];
    const float* edge_w1    = (const float*)d_in[4];
    const float* edge_b1    = (const float*)d_in[5];
    const float* edge_w2    = (const float*)d_in[6];
    const float* edge_b2    = (const float*)d_in[7];
    const float* coord_w1   = (const float*)d_in[8];
    const float* coord_b1   = (const float*)d_in[9];
    const float* coord_w2   = (const float*)d_in[10];
    const float* node_w1    = (const float*)d_in[11];
    const float* node_b1    = (const float*)d_in[12];
    const float* node_w2    = (const float*)d_in[13];
    const float* node_b2    = (const float*)d_in[14];
    const float* fc_node_w  = (const float*)d_in[15];
    const float* fc_node_b  = (const float*)d_in[16];
    const float* fc_edge_w  = (const float*)d_in[17];
    const float* fc_edge_b  = (const float*)d_in[18];
    const float* dec_node_w = (const float*)d_in[19];
    const float* dec_node_b = (const float*)d_in[20];
    const float* dec_edge_w = (const float*)d_in[21];
    const float* dec_edge_b = (const float*)d_in[22];

    float* out = (float*)d_out;
    float* out_node_emb   = out + OFF_NODE_EMB;
    float* out_edge_emb   = out + OFF_EDGE_EMB;
    float* out_recon_node = out + OFF_RECON_NODE;
    float* out_recon_edge = out + OFF_RECON_EDGE;
    float* out_adj        = out + OFF_ADJ;
    float* out_coord      = out + OFF_COORD;

    init_kernel<<<256, 256>>>(coords, out_coord);
    proj_kernel<<<(N_ + 15) / 16, 128>>>(node_feats, edge_w1, edge_b1);
    edge_kernel<<<1184, 128>>>(edge_index, edge_attr, coords,
                               edge_w1, edge_w2, edge_b2,
                               coord_w1, coord_b1, coord_w2,
                               fc_edge_w, fc_edge_b, dec_edge_w, dec_edge_b,
                               out_edge_emb, out_recon_edge, out_coord);
    node_kernel<<<(N_ + 15) / 16, 128>>>(node_feats, out_coord,
                                         node_w1, node_b1, node_w2, node_b2,
                                         fc_node_w, fc_node_b,
                                         dec_node_w, dec_node_b,
                                         out_node_emb, out_recon_node);
    dim3 agrid((N_ + 63) / 64, (N_ + 63) / 64);
    adj_kernel<<<agrid, dim3(16, 16)>>>(out_node_emb, out_adj);
}

// round 3
// speedup vs baseline: 1.0167x; 1.0167x over previous
#include <cuda_runtime.h>
#include <math.h>

// ---------------------------------------------------------------------------
// Problem constants
// ---------------------------------------------------------------------------
static constexpr int N_ = 10000;
static constexpr int E_ = 320000;

static constexpr size_t OFF_NODE_EMB   = 0;
static constexpr size_t OFF_EDGE_EMB   = 80000;
static constexpr size_t OFF_RECON_NODE = 2640000;
static constexpr size_t OFF_RECON_EDGE = 3280000;
static constexpr size_t OFF_ADJ        = 13520000;
static constexpr size_t OFF_COORD      = 113520000;

// ---------------------------------------------------------------------------
// Scratch (__device__ globals; no allocation allowed)
// ---------------------------------------------------------------------------
__device__ __align__(16) float g_P[N_ * 256];   // [0:128)=b1 + nf@W1[0:64], [128:256)=nf@W1[64:128]
__device__ float g_agg[N_ * 32];                // scatter-add of edge_out by row

// ---------------------------------------------------------------------------
// init: zero agg, seed coord_out with coords
// ---------------------------------------------------------------------------
__global__ void init_kernel(const float* __restrict__ coords,
                            float* __restrict__ out_coord)
{
    int i = blockIdx.x * blockDim.x + threadIdx.x;
    int stride = gridDim.x * blockDim.x;
    for (int k = i; k < N_ * 32; k += stride) g_agg[k] = 0.f;
    for (int k = i; k < N_ * 3;  k += stride) out_coord[k] = coords[k];
}

// ---------------------------------------------------------------------------
// Node projections: g_P[n] = [ b1 + nf[n] @ W1[0:64] , nf[n] @ W1[64:128] ]
// 8 nodes per block (grid 1250 for occupancy), thread j owns hidden col j.
// ---------------------------------------------------------------------------
__global__ __launch_bounds__(128) void proj_kernel(
    const float* __restrict__ nf, const float* __restrict__ w1,
    const float* __restrict__ b1)
{
    __shared__ float sIn[8][65];
    int tid = threadIdx.x;
    int n0 = blockIdx.x * 8;
    if (n0 >= N_) return;

    for (int t = tid; t < 8 * 64; t += 128) {
        int g = t >> 6, i = t & 63;
        sIn[g][i] = nf[(n0 + g) * 64 + i];
    }
    __syncthreads();

    float pa[8], pb[8];
    float bb = b1[tid];
#pragma unroll
    for (int g = 0; g < 8; g++) { pa[g] = bb; pb[g] = 0.f; }

    for (int i = 0; i < 64; i++) {
        float wa = w1[i * 128 + tid];
        float wb = w1[(64 + i) * 128 + tid];
#pragma unroll
        for (int g = 0; g < 8; g++) {
            float v = sIn[g][i];
            pa[g] += v * wa;
            pb[g] += v * wb;
        }
    }
#pragma unroll
    for (int g = 0; g < 8; g++) {
        g_P[(size_t)(n0 + g) * 256 + tid]       = pa[g];
        g_P[(size_t)(n0 + g) * 256 + 128 + tid] = pb[g];
    }
}

// ---------------------------------------------------------------------------
// Edge kernel: 256 threads (8 warps share one weight copy), dynamic smem.
// Per warp, 4 edges at a time.
//   h = relu(P_a[row] + P_b[col] + attr @ W1c + radial*w1d)   (128)
//   edge_out = h @ W2 + b2                                     (32)
//   coord weight MLP -> atomic scatter into coord_out
//   atomic scatter edge_out into g_agg
//   edge_emb = edge_out @ fcW + fcb  -> d_out
//   recon_edge = edge_emb @ decW + decb -> d_out
// ---------------------------------------------------------------------------
// smem layout in floats:
static constexpr int SM_W1C  = 0;                 // 32*128 = 4096
static constexpr int SM_W1D  = 4096;              // 128
static constexpr int SM_W2T  = 4224;              // 32*132 = 4224
static constexpr int SM_B2   = 8448;              // 32
static constexpr int SM_CW1  = 8480;              // 64
static constexpr int SM_CM   = 8544;              // 4
static constexpr int SM_FCW  = 8548;              // 256
static constexpr int SM_FCB  = 8804;              // 8
static constexpr int SM_DECW = 8812;              // 256
static constexpr int SM_DECB = 9068;              // 32
static constexpr int SM_H    = 9100;              // 8*4*128 = 4096 (16B aligned: 9100*4=36400)
static constexpr int SM_O    = 13196;             // 8*4*33  = 1056
static constexpr int SM_EMB  = 14252;             // 8*4*8   = 256
static constexpr int SM_TOT  = 14508;             // floats -> 58032 bytes

__global__ __launch_bounds__(256) void edge_kernel(
    const int*   __restrict__ ei,
    const float* __restrict__ edge_attr,
    const float* __restrict__ coords,
    const float* __restrict__ ew1,
    const float* __restrict__ ew2,  const float* __restrict__ eb2,
    const float* __restrict__ cw1,  const float* __restrict__ cb1,
    const float* __restrict__ cw2,
    const float* __restrict__ fcw,  const float* __restrict__ fcb,
    const float* __restrict__ decw, const float* __restrict__ decb,
    float* __restrict__ out_edge_emb,
    float* __restrict__ out_recon_edge,
    float* __restrict__ out_coord)
{
    extern __shared__ __align__(16) float smem[];
    float* sW1c  = smem + SM_W1C;
    float* sW1d  = smem + SM_W1D;
    float* sW2t  = smem + SM_W2T;
    float* sB2   = smem + SM_B2;
    float* sCw1  = smem + SM_CW1;
    float* sCm   = smem + SM_CM;
    float* sFcW  = smem + SM_FCW;
    float* sFcB  = smem + SM_FCB;
    float* sDecW = smem + SM_DECW;
    float* sDecB = smem + SM_DECB;

    int tid = threadIdx.x;
    for (int t = tid; t < 32 * 128; t += 256) sW1c[t] = ew1[128 * 128 + t];
    if (tid < 128) sW1d[tid] = ew1[160 * 128 + tid];
    for (int t = tid; t < 32 * 128; t += 256) {
        int k = t >> 7, j = t & 127;
        sW2t[k * 132 + j] = ew2[j * 32 + k];
    }
    if (tid < 32) sB2[tid] = eb2[tid];
    if (tid < 64) sCw1[tid] = cw1[tid];
    if (tid < 2)  { sCm[tid] = cb1[tid]; sCm[2 + tid] = cw2[tid]; }
    if (tid < 256) { sFcW[tid] = fcw[tid]; sDecW[tid] = decw[tid]; }
    if (tid < 8)  sFcB[tid] = fcb[tid];
    if (tid < 32) sDecB[tid] = decb[tid];
    __syncthreads();

    const int warp = tid >> 5, lane = tid & 31;
    float* sHw = smem + SM_H   + warp * 4 * 128;
    float* sOw = smem + SM_O   + warp * 4 * 33;
    float* sEw = smem + SM_EMB + warp * 4 * 8;
    const int ngroups = E_ / 4;

    for (int grp = blockIdx.x * 8 + warp; grp < ngroups; grp += gridDim.x * 8) {
        const int e0 = grp * 4;
        int row[4];
        float attr[4], nx[4], ny[4], nz[4];
        float4 h[4];

#pragma unroll
        for (int g = 0; g < 4; g++) {
            int e = e0 + g;
            row[g] = ei[e];
            int colg = ei[E_ + e];
            float cx = coords[row[g] * 3 + 0] - coords[colg * 3 + 0];
            float cy = coords[row[g] * 3 + 1] - coords[colg * 3 + 1];
            float cz = coords[row[g] * 3 + 2] - coords[colg * 3 + 2];
            float radial = cx * cx + cy * cy + cz * cz;
            float inv = 1.f / (sqrtf(radial) + 1.f);
            nx[g] = cx * inv; ny[g] = cy * inv; nz[g] = cz * inv;
            attr[g] = edge_attr[(size_t)e * 32 + lane];

            float4 pa = *(const float4*)(g_P + (size_t)row[g] * 256 + 4 * lane);
            float4 pb = *(const float4*)(g_P + (size_t)colg * 256 + 128 + 4 * lane);
            float4 wd = *(const float4*)(sW1d + 4 * lane);
            h[g].x = pa.x + pb.x + radial * wd.x;
            h[g].y = pa.y + pb.y + radial * wd.y;
            h[g].z = pa.z + pb.z + radial * wd.z;
            h[g].w = pa.w + pb.w + radial * wd.w;
        }

        // layer 1: attr part (K=32), attr broadcast via shfl
#pragma unroll 4
        for (int i = 0; i < 32; i++) {
            float4 w = *(const float4*)(sW1c + i * 128 + 4 * lane);
#pragma unroll
            for (int g = 0; g < 4; g++) {
                float a = __shfl_sync(0xffffffffu, attr[g], i);
                h[g].x += a * w.x;
                h[g].y += a * w.y;
                h[g].z += a * w.z;
                h[g].w += a * w.w;
            }
        }

        // relu, stage h
#pragma unroll
        for (int g = 0; g < 4; g++) {
            float4 v;
            v.x = fmaxf(h[g].x, 0.f);
            v.y = fmaxf(h[g].y, 0.f);
            v.z = fmaxf(h[g].z, 0.f);
            v.w = fmaxf(h[g].w, 0.f);
            *(float4*)(sHw + g * 128 + 4 * lane) = v;
        }
        __syncwarp();

        // layer 2: lane owns output channel k = lane
        float out[4];
#pragma unroll
        for (int g = 0; g < 4; g++) out[g] = sB2[lane];
#pragma unroll 4
        for (int j4 = 0; j4 < 32; j4++) {
            float4 w = *(const float4*)(sW2t + lane * 132 + 4 * j4);
#pragma unroll
            for (int g = 0; g < 4; g++) {
                float4 hv = *(const float4*)(sHw + g * 128 + 4 * j4);
                out[g] += w.x * hv.x + w.y * hv.y + w.z * hv.z + w.w * hv.w;
            }
        }

        // scatter edge_out into agg
#pragma unroll
        for (int g = 0; g < 4; g++)
            atomicAdd(&g_agg[(size_t)row[g] * 32 + lane], out[g]);

        // coord MLP + coord scatter
        float c0 = sCm[0], c1 = sCm[1], d0 = sCm[2], d1 = sCm[3];
#pragma unroll
        for (int g = 0; g < 4; g++) {
            float p0 = out[g] * sCw1[lane * 2 + 0];
            float p1 = out[g] * sCw1[lane * 2 + 1];
#pragma unroll
            for (int off = 16; off > 0; off >>= 1) {
                p0 += __shfl_xor_sync(0xffffffffu, p0, off);
                p1 += __shfl_xor_sync(0xffffffffu, p1, off);
            }
            float t0 = fmaxf(p0 + c0, 0.f);
            float t1 = fmaxf(p1 + c1, 0.f);
            float wc = t0 * d0 + t1 * d1;
            if (lane < 3) {
                float nv = (lane == 0) ? nx[g] : ((lane == 1) ? ny[g] : nz[g]);
                atomicAdd(&out_coord[(size_t)row[g] * 3 + lane], nv * wc);
            }
        }

        // stage edge_out for cross-lane matvecs
#pragma unroll
        for (int g = 0; g < 4; g++) sOw[g * 33 + lane] = out[g];
        __syncwarp();

        // edge embedding: lane -> (g = lane>>3, m = lane&7)
        {
            int g = lane >> 3, m = lane & 7;
            float acc = sFcB[m];
#pragma unroll
            for (int k = 0; k < 32; k++) acc += sOw[g * 33 + k] * sFcW[k * 8 + m];
            out_edge_emb[(size_t)(e0 + g) * 8 + m] = acc;
            sEw[g * 8 + m] = acc;
        }
        __syncwarp();

        // recon edge: lane owns output channel k = lane
#pragma unroll
        for (int g = 0; g < 4; g++) {
            float acc = sDecB[lane];
#pragma unroll
            for (int m = 0; m < 8; m++)
                acc += sEw[g * 8 + m] * sDecW[m * 32 + lane];
            out_recon_edge[(size_t)(e0 + g) * 32 + lane] = acc;
        }
        __syncwarp();
    }
}

// ---------------------------------------------------------------------------
// Node kernel: 8 nodes per block (grid 1250 for occupancy).
//   node_in = [nf(64), agg(32), coord_out(3)] -> h(128) -> out(64)
//   -> node_emb(8) -> recon_node(64)
// ---------------------------------------------------------------------------
__global__ __launch_bounds__(128) void node_kernel(
    const float* __restrict__ nf,
    const float* __restrict__ coord_out,
    const float* __restrict__ w1, const float* __restrict__ b1,
    const float* __restrict__ w2, const float* __restrict__ b2,
    const float* __restrict__ fcw, const float* __restrict__ fcb,
    const float* __restrict__ decw, const float* __restrict__ decb,
    float* __restrict__ out_node_emb,
    float* __restrict__ out_recon_node)
{
    __shared__ float sIn[8][100];
    __shared__ float sH[8][128];
    __shared__ float sOut[8][65];
    __shared__ float sEmb[8][9];

    int tid = threadIdx.x;
    int n0 = blockIdx.x * 8;
    if (n0 >= N_) return;

    for (int t = tid; t < 8 * 99; t += 128) {
        int g = t / 99, i = t % 99;
        int n = n0 + g;
        float v;
        if (i < 64)      v = nf[(size_t)n * 64 + i];
        else if (i < 96) v = g_agg[(size_t)n * 32 + (i - 64)];
        else             v = coord_out[(size_t)n * 3 + (i - 96)];
        sIn[g][i] = v;
    }
    __syncthreads();

    // layer 1: thread tid owns hidden column
    {
        float h[8];
        float bb = b1[tid];
#pragma unroll
        for (int g = 0; g < 8; g++) h[g] = bb;
        for (int i = 0; i < 99; i++) {
            float w = w1[i * 128 + tid];
#pragma unroll
            for (int g = 0; g < 8; g++) h[g] += sIn[g][i] * w;
        }
#pragma unroll
        for (int g = 0; g < 8; g++) sH[g][tid] = fmaxf(h[g], 0.f);
    }
    __syncthreads();

    // layer 2: thread -> (k = tid&63, nodes gbase..gbase+3)
    {
        int k = tid & 63;
        int gbase = (tid >> 6) * 4;
        float o[4];
        float bb = b2[k];
#pragma unroll
        for (int q = 0; q < 4; q++) o[q] = bb;
        for (int j = 0; j < 128; j++) {
            float w = w2[j * 64 + k];
#pragma unroll
            for (int q = 0; q < 4; q++) o[q] += sH[gbase + q][j] * w;
        }
#pragma unroll
        for (int q = 0; q < 4; q++) sOut[gbase + q][k] = o[q];
    }
    __syncthreads();

    // embedding: threads 0..63 -> (g = tid>>3, m = tid&7)
    if (tid < 64) {
        int g = tid >> 3, m = tid & 7;
        float acc = fcb[m];
#pragma unroll
        for (int k = 0; k < 64; k++) acc += sOut[g][k] * fcw[k * 8 + m];
        out_node_emb[(size_t)(n0 + g) * 8 + m] = acc;
        sEmb[g][m] = acc;
    }
    __syncthreads();

    // recon node
    {
        int k = tid & 63;
        int gbase = (tid >> 6) * 4;
#pragma unroll
        for (int q = 0; q < 4; q++) {
            int g = gbase + q;
            float acc = decb[k];
#pragma unroll
            for (int m = 0; m < 8; m++) acc += sEmb[g][m] * decw[m * 64 + k];
            out_recon_node[(size_t)(n0 + g) * 64 + k] = acc;
        }
    }
}

// ---------------------------------------------------------------------------
// adj kernel: 64x64 tile per block, 4x4 micro-tile per thread.
//   adj[i][j] = sigmoid(qi + qj - 6*(ei.ej)) with q = 3*r - 0.5; diag 0.
// ---------------------------------------------------------------------------
__global__ __launch_bounds__(256) void adj_kernel(
    const float* __restrict__ emb, float* __restrict__ adj)
{
    __shared__ float sA[64][8];
    __shared__ float sB[64][9];
    __shared__ float sQA[64], sQB[64];

    int tx = threadIdx.x, ty = threadIdx.y;
    int tid = ty * 16 + tx;
    int bi = blockIdx.y * 64, bj = blockIdx.x * 64;

    for (int t = tid; t < 512; t += 256) {
        int r = t >> 3, d = t & 7;
        int gi = bi + r, gj = bj + r;
        sA[r][d] = (gi < N_) ? emb[(size_t)gi * 8 + d] : 0.f;
        sB[r][d] = (gj < N_) ? emb[(size_t)gj * 8 + d] : 0.f;
    }
    __syncthreads();

    if (tid < 64) {
        float s = 0.f;
#pragma unroll
        for (int d = 0; d < 8; d++) s += sA[tid][d] * sA[tid][d];
        sQA[tid] = 3.f * s - 0.5f;
    } else if (tid < 128) {
        int r = tid - 64;
        float s = 0.f;
#pragma unroll
        for (int d = 0; d < 8; d++) s += sB[r][d] * sB[r][d];
        sQB[r] = 3.f * s - 0.5f;
    }
    __syncthreads();

    float a[4][8], b[4][8], qa[4], qb[4];
#pragma unroll
    for (int ii = 0; ii < 4; ii++) {
        qa[ii] = sQA[ty * 4 + ii];
#pragma unroll
        for (int d = 0; d < 8; d++) a[ii][d] = sA[ty * 4 + ii][d];
    }
#pragma unroll
    for (int jj = 0; jj < 4; jj++) {
        qb[jj] = sQB[tx * 4 + jj];
#pragma unroll
        for (int d = 0; d < 8; d++) b[jj][d] = sB[tx * 4 + jj][d];
    }

#pragma unroll
    for (int ii = 0; ii < 4; ii++) {
        int gi = bi + ty * 4 + ii;
        float r4[4];
#pragma unroll
        for (int jj = 0; jj < 4; jj++) {
            float dot = 0.f;
#pragma unroll
            for (int d = 0; d < 8; d++) dot += a[ii][d] * b[jj][d];
            float y = qa[ii] + qb[jj] - 6.f * dot;
            float s = 1.f / (1.f + exp2f(-1.4426950408889634f * y));
            int gj = bj + tx * 4 + jj;
            if (gi == gj) s = 0.f;
            r4[jj] = s;
        }
        if (gi < N_) {
            int gj0 = bj + tx * 4;
            if (gj0 + 3 < N_) {
                *(float4*)(adj + (size_t)gi * N_ + gj0) =
                    make_float4(r4[0], r4[1], r4[2], r4[3]);
            } else {
                for (int jj = 0; jj < 4; jj++)
                    if (gj0 + jj < N_) adj[(size_t)gi * N_ + gj0 + jj] = r4[jj];
            }
        }
    }
}

// ---------------------------------------------------------------------------
// launch
// ---------------------------------------------------------------------------
extern "C" void kernel_launch(void* const* d_in, const int* in_sizes, int n_in,
                              void* d_out, int out_size)
{
    const float* node_feats = (const float*)d_in[0];
    const int*   edge_index = (const int*)  d_in[1];
    const float* edge_attr  = (const float*)d_in[2];
    const float* coords     = (const float*)d_in[3];
    const float* edge_w1    = (const float*)d_in[4];
    const float* edge_b1    = (const float*)d_in[5];
    const float* edge_w2    = (const float*)d_in[6];
    const float* edge_b2    = (const float*)d_in[7];
    const float* coord_w1   = (const float*)d_in[8];
    const float* coord_b1   = (const float*)d_in[9];
    const float* coord_w2   = (const float*)d_in[10];
    const float* node_w1    = (const float*)d_in[11];
    const float* node_b1    = (const float*)d_in[12];
    const float* node_w2    = (const float*)d_in[13];
    const float* node_b2    = (const float*)d_in[14];
    const float* fc_node_w  = (const float*)d_in[15];
    const float* fc_node_b  = (const float*)d_in[16];
    const float* fc_edge_w  = (const float*)d_in[17];
    const float* fc_edge_b  = (const float*)d_in[18];
    const float* dec_node_w = (const float*)d_in[19];
    const float* dec_node_b = (const float*)d_in[20];
    const float* dec_edge_w = (const float*)d_in[21];
    const float* dec_edge_b = (const float*)d_in[22];

    float* out = (float*)d_out;
    float* out_node_emb   = out + OFF_NODE_EMB;
    float* out_edge_emb   = out + OFF_EDGE_EMB;
    float* out_recon_node = out + OFF_RECON_NODE;
    float* out_recon_edge = out + OFF_RECON_EDGE;
    float* out_adj        = out + OFF_ADJ;
    float* out_coord      = out + OFF_COORD;

    static bool attr_set = false;
    if (!attr_set) {
        cudaFuncSetAttribute(edge_kernel,
                             cudaFuncAttributeMaxDynamicSharedMemorySize,
                             SM_TOT * (int)sizeof(float));
        attr_set = true;
    }

    init_kernel<<<256, 256>>>(coords, out_coord);
    proj_kernel<<<(N_ + 7) / 8, 128>>>(node_feats, edge_w1, edge_b1);
    edge_kernel<<<592, 256, SM_TOT * sizeof(float)>>>(
        edge_index, edge_attr, coords,
        edge_w1, edge_w2, edge_b2,
        coord_w1, coord_b1, coord_w2,
        fc_edge_w, fc_edge_b, dec_edge_w, dec_edge_b,
        out_edge_emb, out_recon_edge, out_coord);
    node_kernel<<<(N_ + 7) / 8, 128>>>(node_feats, out_coord,
                                       node_w1, node_b1, node_w2, node_b2,
                                       fc_node_w, fc_node_b,
                                       dec_node_w, dec_node_b,
                                       out_node_emb, out_recon_node);
    dim3 agrid((N_ + 63) / 64, (N_ + 63) / 64);
    adj_kernel<<<agrid, dim3(16, 16)>>>(out_node_emb, out_adj);
}